// round 3
// baseline (speedup 1.0000x reference)
#include <cuda_runtime.h>
#include <cstdint>

#define EPS    1e-5f
#define V_DIM  32
#define D_DIM  128
#define NPER   16          // n-units (16KB each) per CTA

// ---------------------------------------------------------------------------
// 1024-thread CTA = 32 warps; warp w owns variable v = w.
// Lanes hold W/b/gamma/beta[v, lane*4 .. lane*4+3] in registers; warp computes
// per-v stats once via shuffles (analytic LayerNorm, no per-row reduction):
//   h  = x*W + b
//   mu = x*Wbar + bbar
//   var= x^2*Var(W) + 2x*Cov(W,b) + Var(b)
// Rows are staged in smem (one n-unit = all 32 v = 16KB contiguous in out)
// and written with cp.async.bulk S2G, bypassing the L1tex STG path.
// ---------------------------------------------------------------------------
__global__ void __launch_bounds__(1024, 1)
ve_kernel(const float* __restrict__ x,
          const float* __restrict__ W,
          const float* __restrict__ b,
          const float* __restrict__ gamma,
          const float* __restrict__ beta,
          float* __restrict__ out) {
    __shared__ __align__(128) float sbuf[2][V_DIM * D_DIM];  // 2 x 16KB

    int v    = threadIdx.x >> 5;     // warp id = variable index
    int lane = threadIdx.x & 31;

    int t = v * 32 + lane;           // [V, D/4] table index
    float4 w4 = __ldg(reinterpret_cast<const float4*>(W)     + t);
    float4 b4 = __ldg(reinterpret_cast<const float4*>(b)     + t);
    float4 g4 = __ldg(reinterpret_cast<const float4*>(gamma) + t);
    float4 e4 = __ldg(reinterpret_cast<const float4*>(beta)  + t);

    // ---- per-v stats via butterfly reductions ----
    float sw = w4.x + w4.y + w4.z + w4.w;
    float sb = b4.x + b4.y + b4.z + b4.w;
    #pragma unroll
    for (int off = 16; off > 0; off >>= 1) {
        sw += __shfl_xor_sync(0xFFFFFFFFu, sw, off);
        sb += __shfl_xor_sync(0xFFFFFFFFu, sb, off);
    }
    float Wbar = sw * (1.0f / D_DIM);
    float bbar = sb * (1.0f / D_DIM);

    float wc0 = w4.x - Wbar, wc1 = w4.y - Wbar, wc2 = w4.z - Wbar, wc3 = w4.w - Wbar;
    float bc0 = b4.x - bbar, bc1 = b4.y - bbar, bc2 = b4.z - bbar, bc3 = b4.w - bbar;
    float sww = wc0*wc0 + wc1*wc1 + wc2*wc2 + wc3*wc3;
    float swb = wc0*bc0 + wc1*bc1 + wc2*bc2 + wc3*bc3;
    float sbb = bc0*bc0 + bc1*bc1 + bc2*bc2 + bc3*bc3;
    #pragma unroll
    for (int off = 16; off > 0; off >>= 1) {
        sww += __shfl_xor_sync(0xFFFFFFFFu, sww, off);
        swb += __shfl_xor_sync(0xFFFFFFFFu, swb, off);
        sbb += __shfl_xor_sync(0xFFFFFFFFu, sbb, off);
    }
    float varW = sww * (1.0f / D_DIM);
    float cov2 = swb * (2.0f / D_DIM);   // 2*Cov(W,b)
    float varb = sbb * (1.0f / D_DIM);

    const float* xp = x + v;             // x[n*V + v]
    int n0 = blockIdx.x * NPER;

    // smem addresses of the two staging buffers (shared-state-space u32)
    uint32_t sa[2];
    #pragma unroll
    for (int bnum = 0; bnum < 2; bnum++) {
        asm("{ .reg .u64 tt; cvta.to.shared.u64 tt, %1; cvt.u32.u64 %0, tt; }"
            : "=r"(sa[bnum]) : "l"(&sbuf[bnum][0]));
    }

    for (int i = 0; i < NPER; i++) {
        int n  = n0 + i;
        int bf = i & 1;

        // ---- compute this warp's 512B row (overlaps with in-flight copies) --
        float xv  = __ldg(xp + n * V_DIM);
        float var = fmaf(xv, fmaf(xv, varW, cov2), varb);
        float rs  = rsqrtf(var + EPS);
        float mu  = fmaf(xv, Wbar, bbar);
        float nmr = -mu * rs;            // (h-mu)*rs == fma(h, rs, nmr)

        float4 o;
        { float h = fmaf(w4.x, xv, b4.x); float y = fmaf(h, rs, nmr);
          o.x = fmaxf(fmaf(g4.x, y, e4.x), 0.0f); }
        { float h = fmaf(w4.y, xv, b4.y); float y = fmaf(h, rs, nmr);
          o.y = fmaxf(fmaf(g4.y, y, e4.y), 0.0f); }
        { float h = fmaf(w4.z, xv, b4.z); float y = fmaf(h, rs, nmr);
          o.z = fmaxf(fmaf(g4.z, y, e4.z), 0.0f); }
        { float h = fmaf(w4.w, xv, b4.w); float y = fmaf(h, rs, nmr);
          o.w = fmaxf(fmaf(g4.w, y, e4.w), 0.0f); }

        // ---- backpressure: buffer bf free once <=1 copy is outstanding ----
        if (threadIdx.x == 0) {
            asm volatile("cp.async.bulk.wait_group.read 1;" ::: "memory");
        }
        __syncthreads();

        // ---- stage into smem (layout == gmem layout for this n-unit) ----
        reinterpret_cast<float4*>(&sbuf[bf][v * D_DIM])[lane] = o;
        __syncthreads();

        // ---- bulk copy 16KB smem -> gmem ----
        if (threadIdx.x == 0) {
            asm volatile("fence.proxy.async.shared::cta;" ::: "memory");
            const float* gdst = out + (size_t)n * (V_DIM * D_DIM);
            int bytes = V_DIM * D_DIM * 4;
            asm volatile(
                "cp.async.bulk.global.shared::cta.bulk_group [%0], [%1], %2;"
                :: "l"(gdst), "r"(sa[bf]), "r"(bytes) : "memory");
            asm volatile("cp.async.bulk.commit_group;" ::: "memory");
        }
    }

    if (threadIdx.x == 0) {
        asm volatile("cp.async.bulk.wait_group.read 0;" ::: "memory");
    }
}

// ---------------------------------------------------------------------------
extern "C" void kernel_launch(void* const* d_in, const int* in_sizes, int n_in,
                              void* d_out, int out_size) {
    const float* x     = (const float*)d_in[0];
    const float* W     = (const float*)d_in[1];
    const float* b     = (const float*)d_in[2];
    const float* gamma = (const float*)d_in[3];
    const float* beta  = (const float*)d_in[4];
    float* out = (float*)d_out;

    // n-units of 16KB: out_size / (V*D) = 32768 ; blocks = 32768/NPER = 2048
    int n_units = out_size / (V_DIM * D_DIM);
    int blocks  = n_units / NPER;

    ve_kernel<<<blocks, 1024>>>(x, W, b, gamma, beta, out);
}

// round 4
// speedup vs baseline: 1.3098x; 1.3098x over previous
#include <cuda_runtime.h>

#define EPS    1e-5f
#define V_DIM  32
#define D_DIM  128
#define ITERS  32          // n-units per CTA

// ---------------------------------------------------------------------------
// 1024-thread CTA = 32 warps; warp w owns variable v = w. Lanes hold
// W/b/gamma/beta[v, lane*4..lane*4+3] in registers; warp computes per-v stats
// once via shuffles (analytic LayerNorm — no per-row reduction):
//   h  = x*W + b
//   mu = x*Wbar + bbar
//   var= x^2*Var(W) + 2x*Cov(W,b) + Var(b)
// Each iteration the CTA writes one full contiguous 16KB n-unit with
// evict-first (streaming) STG.128 — output is write-once, keep it out of L2.
// No barriers: warps are fully independent.
// ---------------------------------------------------------------------------
__global__ void __launch_bounds__(1024, 1)
ve_kernel(const float* __restrict__ x,
          const float* __restrict__ W,
          const float* __restrict__ b,
          const float* __restrict__ gamma,
          const float* __restrict__ beta,
          float* __restrict__ out) {
    int v    = threadIdx.x >> 5;     // warp id = variable index
    int lane = threadIdx.x & 31;

    int t = v * 32 + lane;           // [V, D/4] table index
    float4 w4 = __ldg(reinterpret_cast<const float4*>(W)     + t);
    float4 b4 = __ldg(reinterpret_cast<const float4*>(b)     + t);
    float4 g4 = __ldg(reinterpret_cast<const float4*>(gamma) + t);
    float4 e4 = __ldg(reinterpret_cast<const float4*>(beta)  + t);

    // ---- per-v stats via butterfly reductions ----
    float sw = w4.x + w4.y + w4.z + w4.w;
    float sb = b4.x + b4.y + b4.z + b4.w;
    #pragma unroll
    for (int off = 16; off > 0; off >>= 1) {
        sw += __shfl_xor_sync(0xFFFFFFFFu, sw, off);
        sb += __shfl_xor_sync(0xFFFFFFFFu, sb, off);
    }
    float Wbar = sw * (1.0f / D_DIM);
    float bbar = sb * (1.0f / D_DIM);

    float wc0 = w4.x - Wbar, wc1 = w4.y - Wbar, wc2 = w4.z - Wbar, wc3 = w4.w - Wbar;
    float bc0 = b4.x - bbar, bc1 = b4.y - bbar, bc2 = b4.z - bbar, bc3 = b4.w - bbar;
    float sww = wc0*wc0 + wc1*wc1 + wc2*wc2 + wc3*wc3;
    float swb = wc0*bc0 + wc1*bc1 + wc2*bc2 + wc3*bc3;
    float sbb = bc0*bc0 + bc1*bc1 + bc2*bc2 + bc3*bc3;
    #pragma unroll
    for (int off = 16; off > 0; off >>= 1) {
        sww += __shfl_xor_sync(0xFFFFFFFFu, sww, off);
        swb += __shfl_xor_sync(0xFFFFFFFFu, swb, off);
        sbb += __shfl_xor_sync(0xFFFFFFFFu, sbb, off);
    }
    float varW = sww * (1.0f / D_DIM);
    float cov2 = swb * (2.0f / D_DIM);   // 2*Cov(W,b)
    float varb = sbb * (1.0f / D_DIM);

    const float* xp = x + v;             // x[n*V + v]
    int n0 = blockIdx.x * ITERS;
    // this warp's output base: out + (n*V + v)*D, as float4 rows of 32
    float4* orow = reinterpret_cast<float4*>(out) + ((size_t)n0 * V_DIM + v) * 32 + lane;

    #pragma unroll 4
    for (int i = 0; i < ITERS; i++) {
        float xv  = __ldg(xp + (n0 + i) * V_DIM);

        float var = fmaf(xv, fmaf(xv, varW, cov2), varb);
        float rs  = rsqrtf(var + EPS);
        float mu  = fmaf(xv, Wbar, bbar);
        float nmr = -mu * rs;            // (h-mu)*rs == fma(h, rs, nmr)

        float4 o;
        { float h = fmaf(w4.x, xv, b4.x); float y = fmaf(h, rs, nmr);
          o.x = fmaxf(fmaf(g4.x, y, e4.x), 0.0f); }
        { float h = fmaf(w4.y, xv, b4.y); float y = fmaf(h, rs, nmr);
          o.y = fmaxf(fmaf(g4.y, y, e4.y), 0.0f); }
        { float h = fmaf(w4.z, xv, b4.z); float y = fmaf(h, rs, nmr);
          o.z = fmaxf(fmaf(g4.z, y, e4.z), 0.0f); }
        { float h = fmaf(w4.w, xv, b4.w); float y = fmaf(h, rs, nmr);
          o.w = fmaxf(fmaf(g4.w, y, e4.w), 0.0f); }

        // evict-first streaming store: output is write-once, never re-read
        __stcs(orow + (size_t)i * (V_DIM * 32), o);
    }
}

// ---------------------------------------------------------------------------
extern "C" void kernel_launch(void* const* d_in, const int* in_sizes, int n_in,
                              void* d_out, int out_size) {
    const float* x     = (const float*)d_in[0];
    const float* W     = (const float*)d_in[1];
    const float* b     = (const float*)d_in[2];
    const float* gamma = (const float*)d_in[3];
    const float* beta  = (const float*)d_in[4];
    float* out = (float*)d_out;

    // n-units (16KB each) = out_size / (V*D) = 32768 ; blocks = 32768/ITERS
    int n_units = out_size / (V_DIM * D_DIM);
    int blocks  = n_units / ITERS;       // 1024

    ve_kernel<<<blocks, 1024>>>(x, W, b, gamma, beta, out);
}